// round 5
// baseline (speedup 1.0000x reference)
#include <cuda_runtime.h>
#include <math.h>

// ---------------------------------------------------------------------------
// Fully-fused KAN generator, one block per batch sample (512 blocks x 256 thr).
//   h0 = relu(x @ lin_w.T + lin_b)  -> SMEM act[16]   ([c][y][x], 4x2x2)
//   stage<2>  : up2 + kan_conv -> act[64]
//   stage<4>  : up2 + kan_conv -> act[256]
//   stage<8>  : up2 + kan_conv -> act[1024]
//   stage<16> : up2 + kan_conv -> tanh -> global out [3,32,32]
//
// Phase C: parity p = tid>>6 is warp-uniform. Each lane owns NJ CONTIGUOUS
// output rows (same X), so NJ outputs share NJ+1 source rows: feature loads
// drop to (NJ+1)/2NJ of the naive count, and each weight float4 is loaded
// once (broadcast) per row-group via the f-outer loop. Out-of-bounds source
// pixels read a guard feature slot (index 1024) holding spline(0) features.
// Stage 4 is COUT=3-specialized (no wasted 4th-channel FMA).
// ---------------------------------------------------------------------------

__device__ __forceinline__ void spline_feats(float v, float4& fa, float2& fb) {
    const float H = 2.0f / 3.0f;
    float g[8];
#pragma unroll
    for (int i = 0; i < 8; i++) g[i] = (float)(i - 2) * H - 1.0f;
    float b0[7];
#pragma unroll
    for (int i = 0; i < 7; i++)
        b0[i] = (v >= g[i] && v < g[i + 1]) ? 1.0f : 0.0f;
    float b1[6];
#pragma unroll
    for (int i = 0; i < 6; i++)
        b1[i] = (v - g[i]) * (1.0f / (g[i + 1] - g[i])) * b0[i]
              + (g[i + 2] - v) * (1.0f / (g[i + 2] - g[i + 1])) * b0[i + 1];
    float b2[5];
#pragma unroll
    for (int i = 0; i < 5; i++)
        b2[i] = (v - g[i]) * (1.0f / (g[i + 2] - g[i])) * b1[i]
              + (g[i + 3] - v) * (1.0f / (g[i + 3] - g[i + 1])) * b1[i + 1];
    fa = make_float4(b2[0], b2[1], b2[2], b2[3]);
    fb = make_float2(b2[4], fmaxf(v, 0.0f));
}

template <int COUT>
__device__ __forceinline__ void fmaC(float s, float4 w, float4& a) {
    a.x = fmaf(s, w.x, a.x);
    a.y = fmaf(s, w.y, a.y);
    a.z = fmaf(s, w.z, a.z);
    if (COUT == 4) a.w = fmaf(s, w.w, a.w);
}

__device__ __forceinline__ float fget(int f, const float4& fa, const float2& fb) {
    return (f == 0) ? fa.x : (f == 1) ? fa.y : (f == 2) ? fa.z
         : (f == 3) ? fa.w : (f == 4) ? fb.x : fb.y;
}

// ----------------------------- one conv stage ------------------------------
template <int HIN, int COUT, bool FINAL>
__device__ __forceinline__ void do_stage(
    const float* __restrict__ bw, const float* __restrict__ sw,
    float* act, float4* featA, float2* featB,
    float4* wsh4, float* gout)
{
    constexpr int S2   = HIN * HIN;
    constexpr int NSRC = 4 * S2;
    constexpr int HOUT = 2 * HIN;
    constexpr int NJ   = (S2 >= 64) ? S2 / 64 : 1;  // contiguous rows/thread
    const int tid = threadIdx.x;
    float* wsh = reinterpret_cast<float*>(wsh4);

    // --- build combined weights: W[p][pos][c][wf][co], wf: 0-4 spline, 5 relu
#pragma unroll
    for (int k = 0; k < 6; k++) {
        int e   = tid + k * 256;
        int co  = e & 3;
        int wf  = (e >> 2) % 6;
        int c   = (e / 24) & 3;
        int pos = (e / 96) & 3;
        int p   = e / 384;
        int py = p >> 1, px = p & 1;
        int ry = pos >> 1, rx = pos & 1;
        float s = 0.0f;
        if (co < COUT) {
            int ky0 = ry * (1 + py), nky = 1 + (ry ^ py);
            int kx0 = rx * (1 + px), nkx = 1 + (rx ^ px);
            for (int a = 0; a < nky; a++)
                for (int bb = 0; bb < nkx; bb++) {
                    int j = c * 9 + (ky0 + a) * 3 + (kx0 + bb);
                    s += (wf == 5) ? bw[co * 36 + j]
                                   : sw[(co * 36 + j) * 5 + wf];
                }
        }
        wsh[e] = s;
    }

    // --- featurize source values (reads act)
#pragma unroll
    for (int k = 0; k < (NSRC + 255) / 256; k++) {
        int lv = tid + k * 256;
        if (NSRC >= 256 || lv < NSRC)
            spline_feats(act[lv], featA[lv], featB[lv]);
    }
    __syncthreads();

    // --- phase C: parity-group tiling, NJ contiguous rows per thread
    const int p  = tid >> 6;       // warp-uniform parity
    const int l  = tid & 63;
    const int py = p >> 1, px = p & 1;

    if (S2 >= 64 || l < S2) {
        const int X  = l % HIN;
        const int g  = l / HIN;
        const int Y0 = g * NJ;
        const int rowbase = Y0 - 1 + py;

        float4 acc[NJ];
#pragma unroll
        for (int j = 0; j < NJ; j++) acc[j] = make_float4(0.f, 0.f, 0.f, 0.f);

#pragma unroll
        for (int c = 0; c < 4; c++) {
#pragma unroll
            for (int d = 0; d < 2; d++) {
                const int sx = X - 1 + px + d;
                const bool vx = (unsigned)sx < (unsigned)HIN;
                // load NJ+1 source-row features (guard slot 1024 = spline(0))
                float4 fa[NJ + 1];
                float2 fb[NJ + 1];
#pragma unroll
                for (int r = 0; r <= NJ; r++) {
                    int sy = rowbase + r;
                    bool v = vx && ((unsigned)sy < (unsigned)HIN);
                    int idx = v ? (c * S2 + sy * HIN + sx) : 1024;
                    fa[r] = featA[idx];
                    fb[r] = featB[idx];
                }
                const float4* w0 = wsh4 + ((p * 4 + d) * 4 + c) * 6;      // ry=0
                const float4* w1 = wsh4 + ((p * 4 + 2 + d) * 4 + c) * 6;  // ry=1
#pragma unroll
                for (int f = 0; f < 6; f++) {
                    float4 wv0 = w0[f];
                    float4 wv1 = w1[f];
#pragma unroll
                    for (int r = 0; r <= NJ; r++) {
                        float s = fget(f, fa[r], fb[r]);
                        if (r < NJ)  fmaC<COUT>(s, wv0, acc[r]);
                        if (r >= 1)  fmaC<COUT>(s, wv1, acc[r - 1]);
                    }
                }
            }
        }

        // --- write outputs
#pragma unroll
        for (int j = 0; j < NJ; j++) {
            int y = 2 * (Y0 + j) + py, x = 2 * X + px;
            if (FINAL) {
                gout[0 * HOUT * HOUT + y * HOUT + x] = tanhf(acc[j].x);
                gout[1 * HOUT * HOUT + y * HOUT + x] = tanhf(acc[j].y);
                gout[2 * HOUT * HOUT + y * HOUT + x] = tanhf(acc[j].z);
            } else {
                act[0 * HOUT * HOUT + y * HOUT + x] = acc[j].x;
                act[1 * HOUT * HOUT + y * HOUT + x] = acc[j].y;
                act[2 * HOUT * HOUT + y * HOUT + x] = acc[j].z;
                act[3 * HOUT * HOUT + y * HOUT + x] = acc[j].w;
            }
        }
    }
    __syncthreads();   // act/wsh/feat stable before next stage
}

// ----------------------------- fused kernel --------------------------------
__global__ void __launch_bounds__(256, 3) fused_kan_kernel(
    const float* __restrict__ x,
    const float* __restrict__ lin_w,
    const float* __restrict__ lin_b,
    const float* __restrict__ bw1, const float* __restrict__ sw1,
    const float* __restrict__ bw2, const float* __restrict__ sw2,
    const float* __restrict__ bw3, const float* __restrict__ sw3,
    const float* __restrict__ bw4, const float* __restrict__ sw4,
    float* __restrict__ out)
{
    __shared__ float  act[1024];
    __shared__ float4 featA[1025];   // slot 1024 = spline(0) guard
    __shared__ float2 featB[1025];
    __shared__ float4 wsh4[384];

    const int tid = threadIdx.x;
    const int b   = blockIdx.x;

    if (tid == 0) {
        // guard slot: quadratic B-spline bases at v=0: {0,1/8,3/4,1/8,0}, relu 0
        featA[1024] = make_float4(0.0f, 0.125f, 0.75f, 0.125f);
        featB[1024] = make_float2(0.0f, 0.0f);
    }

    // linear + relu: 16 outputs, 4 threads each over 25-element chunks
    if (tid < 64) {
        int j = tid >> 2, qp = tid & 3;
        const float* xr = x + b * 100 + qp * 25;
        const float* wr = lin_w + j * 100 + qp * 25;
        float acc = 0.0f;
#pragma unroll
        for (int i = 0; i < 25; i++) acc = fmaf(xr[i], wr[i], acc);
        acc += __shfl_xor_sync(0xffffffffu, acc, 1);
        acc += __shfl_xor_sync(0xffffffffu, acc, 2);
        if (qp == 0) act[j] = fmaxf(acc + lin_b[j], 0.0f);
    }
    __syncthreads();

    do_stage<2, 4, false>(bw1, sw1, act, featA, featB, wsh4, nullptr);
    do_stage<4, 4, false>(bw2, sw2, act, featA, featB, wsh4, nullptr);
    do_stage<8, 4, false>(bw3, sw3, act, featA, featB, wsh4, nullptr);
    do_stage<16, 3, true>(bw4, sw4, act, featA, featB, wsh4,
                          out + (size_t)b * 3 * 32 * 32);
}

// ---------------------------------------------------------------------------
extern "C" void kernel_launch(void* const* d_in, const int* in_sizes, int n_in,
                              void* d_out, int out_size) {
    const float* x     = (const float*)d_in[0];
    const float* lin_w = (const float*)d_in[1];
    const float* lin_b = (const float*)d_in[2];
    const float* bw1   = (const float*)d_in[3];
    const float* sw1   = (const float*)d_in[4];
    const float* bw2   = (const float*)d_in[5];
    const float* sw2   = (const float*)d_in[6];
    const float* bw3   = (const float*)d_in[7];
    const float* sw3   = (const float*)d_in[8];
    const float* bw4   = (const float*)d_in[9];
    const float* sw4   = (const float*)d_in[10];

    fused_kan_kernel<<<512, 256>>>(x, lin_w, lin_b,
                                   bw1, sw1, bw2, sw2, bw3, sw3, bw4, sw4,
                                   (float*)d_out);
}

// round 6
// speedup vs baseline: 1.2687x; 1.2687x over previous
#include <cuda_runtime.h>
#include <math.h>

// ---------------------------------------------------------------------------
// Fully-fused KAN generator, one block per batch sample (512 blocks x 256 thr).
//   h0 = relu(x @ lin_w.T + lin_b)  -> SMEM act[16]   ([c][y][x], 4x2x2)
//   stage<2>  : up2 + kan_conv -> act[64]
//   stage<4>  : up2 + kan_conv -> act[256]
//   stage<8>  : up2 + kan_conv -> act[1024]
//   stage<16> : up2 + kan_conv -> tanh -> global out [3,32,32]
//
// Phase C (R4 structure): parity p = tid>>6 is warp-uniform; each 64-lane
// group covers its parity's S2 pixels with NPX = S2/64 strided pixels per
// thread, so every warp-uniform weight float4 is loaded ONCE per NPX pixels.
// Out-of-bounds source pixels use compile-time spline(0) feature constants.
// Stage 4 is COUT=3-specialized (no dead 4th-channel FMA).
// ---------------------------------------------------------------------------

// quadratic B-spline bases evaluated at v=0: b2 = {0, 1/8, 3/4, 1/8, 0}; relu(0)=0
#define F0A make_float4(0.0f, 0.125f, 0.75f, 0.125f)
#define F0B make_float2(0.0f, 0.0f)

__device__ __forceinline__ void spline_feats(float v, float4& fa, float2& fb) {
    const float H = 2.0f / 3.0f;
    float g[8];
#pragma unroll
    for (int i = 0; i < 8; i++) g[i] = (float)(i - 2) * H - 1.0f;
    float b0[7];
#pragma unroll
    for (int i = 0; i < 7; i++)
        b0[i] = (v >= g[i] && v < g[i + 1]) ? 1.0f : 0.0f;
    float b1[6];
#pragma unroll
    for (int i = 0; i < 6; i++)
        b1[i] = (v - g[i]) * (1.0f / (g[i + 1] - g[i])) * b0[i]
              + (g[i + 2] - v) * (1.0f / (g[i + 2] - g[i + 1])) * b0[i + 1];
    float b2[5];
#pragma unroll
    for (int i = 0; i < 5; i++)
        b2[i] = (v - g[i]) * (1.0f / (g[i + 2] - g[i])) * b1[i]
              + (g[i + 3] - v) * (1.0f / (g[i + 3] - g[i + 1])) * b1[i + 1];
    fa = make_float4(b2[0], b2[1], b2[2], b2[3]);
    fb = make_float2(b2[4], fmaxf(v, 0.0f));
}

template <int COUT>
__device__ __forceinline__ void fmaC(float s, float4 w, float4& a) {
    a.x = fmaf(s, w.x, a.x);
    a.y = fmaf(s, w.y, a.y);
    a.z = fmaf(s, w.z, a.z);
    if (COUT == 4) a.w = fmaf(s, w.w, a.w);
}

// ----------------------------- one conv stage ------------------------------
template <int HIN, int COUT, bool FINAL>
__device__ __forceinline__ void do_stage(
    const float* __restrict__ bw, const float* __restrict__ sw,
    float* act, float4* featA, float2* featB,
    float4* wsh4, float* gout)
{
    constexpr int S2   = HIN * HIN;
    constexpr int NSRC = 4 * S2;
    constexpr int HOUT = 2 * HIN;
    constexpr int NPX  = (S2 > 64) ? S2 / 64 : 1;  // pixels per thread
    const int tid = threadIdx.x;
    float* wsh = reinterpret_cast<float*>(wsh4);

    // --- build combined weights: W[p][pos][c][wf][co], wf: 0-4 spline, 5 relu
#pragma unroll
    for (int k = 0; k < 6; k++) {
        int e   = tid + k * 256;
        int co  = e & 3;
        int wf  = (e >> 2) % 6;
        int c   = (e / 24) & 3;
        int pos = (e / 96) & 3;
        int p   = e / 384;
        int py = p >> 1, px = p & 1;
        int ry = pos >> 1, rx = pos & 1;
        float s = 0.0f;
        if (co < COUT) {
            int ky0 = ry * (1 + py), nky = 1 + (ry ^ py);
            int kx0 = rx * (1 + px), nkx = 1 + (rx ^ px);
            for (int a = 0; a < nky; a++)
                for (int bb = 0; bb < nkx; bb++) {
                    int j = c * 9 + (ky0 + a) * 3 + (kx0 + bb);
                    s += (wf == 5) ? bw[co * 36 + j]
                                   : sw[(co * 36 + j) * 5 + wf];
                }
        }
        wsh[e] = s;
    }

    // --- featurize source values (reads act)
#pragma unroll
    for (int k = 0; k < (NSRC + 255) / 256; k++) {
        int lv = tid + k * 256;
        if (NSRC >= 256 || lv < NSRC)
            spline_feats(act[lv], featA[lv], featB[lv]);
    }
    __syncthreads();

    // --- phase C: parity-group tiling, NPX pixels per thread, weights
    //     loaded once per NPX pixels (warp-uniform broadcast)
    const int p  = tid >> 6;       // warp-uniform parity
    const int l  = tid & 63;
    const int py = p >> 1, px = p & 1;

    if (S2 >= 64 || l < S2) {
        const int Yb = l / HIN;    // base row for this thread
        const int X  = l % HIN;    // column (same for all NPX pixels)
        float4 acc[NPX];
#pragma unroll
        for (int j = 0; j < NPX; j++) acc[j] = make_float4(0.f, 0.f, 0.f, 0.f);

#pragma unroll
        for (int pos = 0; pos < 4; pos++) {
            const int ry = pos >> 1, rx = pos & 1;
            const int sx = X - 1 + px + rx;
            const bool vx = (unsigned)sx < (unsigned)HIN;
            int  syj[NPX];
            bool vj[NPX];
#pragma unroll
            for (int j = 0; j < NPX; j++) {
                syj[j] = Yb + j * (64 / HIN) - 1 + py + ry;
                vj[j]  = vx && ((unsigned)syj[j] < (unsigned)HIN);
            }
            const float4* wp = wsh4 + (p * 4 + pos) * 24;
#pragma unroll
            for (int c = 0; c < 4; c++) {
                float4 fa[NPX];
                float2 fb[NPX];
#pragma unroll
                for (int j = 0; j < NPX; j++) {
                    if (vj[j]) {
                        int idx = c * S2 + syj[j] * HIN + sx;
                        fa[j] = featA[idx];
                        fb[j] = featB[idx];
                    } else {
                        fa[j] = F0A;      // spline(0) bases, relu(0)=0
                        fb[j] = F0B;
                    }
                }
                const float4* w = wp + c * 6;
#pragma unroll
                for (int f = 0; f < 6; f++) {
                    float4 wv = w[f];
#pragma unroll
                    for (int j = 0; j < NPX; j++) {
                        float s = (f == 0) ? fa[j].x : (f == 1) ? fa[j].y
                                : (f == 2) ? fa[j].z : (f == 3) ? fa[j].w
                                : (f == 4) ? fb[j].x : fb[j].y;
                        fmaC<COUT>(s, wv, acc[j]);
                    }
                }
            }
        }

        // --- write outputs
#pragma unroll
        for (int j = 0; j < NPX; j++) {
            int q = l + 64 * j;
            int Y = q / HIN, Xo = q % HIN;
            int y = 2 * Y + py, x = 2 * Xo + px;
            if (FINAL) {
                gout[0 * HOUT * HOUT + y * HOUT + x] = tanhf(acc[j].x);
                gout[1 * HOUT * HOUT + y * HOUT + x] = tanhf(acc[j].y);
                gout[2 * HOUT * HOUT + y * HOUT + x] = tanhf(acc[j].z);
            } else {
                act[0 * HOUT * HOUT + y * HOUT + x] = acc[j].x;
                act[1 * HOUT * HOUT + y * HOUT + x] = acc[j].y;
                act[2 * HOUT * HOUT + y * HOUT + x] = acc[j].z;
                act[3 * HOUT * HOUT + y * HOUT + x] = acc[j].w;
            }
        }
    }
    __syncthreads();   // act/wsh/feat stable before next stage
}

// ----------------------------- fused kernel --------------------------------
__global__ void __launch_bounds__(256, 4) fused_kan_kernel(
    const float* __restrict__ x,
    const float* __restrict__ lin_w,
    const float* __restrict__ lin_b,
    const float* __restrict__ bw1, const float* __restrict__ sw1,
    const float* __restrict__ bw2, const float* __restrict__ sw2,
    const float* __restrict__ bw3, const float* __restrict__ sw3,
    const float* __restrict__ bw4, const float* __restrict__ sw4,
    float* __restrict__ out)
{
    __shared__ float  act[1024];
    __shared__ float4 featA[1024];
    __shared__ float2 featB[1024];
    __shared__ float4 wsh4[384];

    const int tid = threadIdx.x;
    const int b   = blockIdx.x;

    // linear + relu: 16 outputs, 4 threads each over 25-element chunks
    if (tid < 64) {
        int j = tid >> 2, qp = tid & 3;
        const float* xr = x + b * 100 + qp * 25;
        const float* wr = lin_w + j * 100 + qp * 25;
        float acc = 0.0f;
#pragma unroll
        for (int i = 0; i < 25; i++) acc = fmaf(xr[i], wr[i], acc);
        acc += __shfl_xor_sync(0xffffffffu, acc, 1);
        acc += __shfl_xor_sync(0xffffffffu, acc, 2);
        if (qp == 0) act[j] = fmaxf(acc + lin_b[j], 0.0f);
    }
    __syncthreads();

    do_stage<2, 4, false>(bw1, sw1, act, featA, featB, wsh4, nullptr);
    do_stage<4, 4, false>(bw2, sw2, act, featA, featB, wsh4, nullptr);
    do_stage<8, 4, false>(bw3, sw3, act, featA, featB, wsh4, nullptr);
    do_stage<16, 3, true>(bw4, sw4, act, featA, featB, wsh4,
                          out + (size_t)b * 3 * 32 * 32);
}

// ---------------------------------------------------------------------------
extern "C" void kernel_launch(void* const* d_in, const int* in_sizes, int n_in,
                              void* d_out, int out_size) {
    const float* x     = (const float*)d_in[0];
    const float* lin_w = (const float*)d_in[1];
    const float* lin_b = (const float*)d_in[2];
    const float* bw1   = (const float*)d_in[3];
    const float* sw1   = (const float*)d_in[4];
    const float* bw2   = (const float*)d_in[5];
    const float* sw2   = (const float*)d_in[6];
    const float* bw3   = (const float*)d_in[7];
    const float* sw3   = (const float*)d_in[8];
    const float* bw4   = (const float*)d_in[9];
    const float* sw4   = (const float*)d_in[10];

    fused_kan_kernel<<<512, 256>>>(x, lin_w, lin_b,
                                   bw1, sw1, bw2, sw2, bw3, sw3, bw4, sw4,
                                   (float*)d_out);
}

// round 7
// speedup vs baseline: 1.2698x; 1.0009x over previous
#include <cuda_runtime.h>
#include <math.h>

// ---------------------------------------------------------------------------
// Fully-fused KAN generator, one block per batch sample (512 blocks x 256 thr).
//   h0 = relu(x @ lin_w.T + lin_b)  -> SMEM act[16]   ([c][y][x], 4x2x2)
//   stage<2>  : up2 + kan_conv -> act[64]
//   stage<4>  : up2 + kan_conv -> act[256]
//   stage<8>  : up2 + kan_conv -> act[1024]
//   stage<16> : up2 + kan_conv -> tanh -> global out [3,32,32]
//
// Features live in HALOED arrays: per channel (HIN+2)x(HIN+2), border ring
// pre-filled with spline(0) features (= zero-padding contribution). Phase C
// does NO bounds checks: every feature load is LDS [base + compile-time
// offset], one IMAD per thread per stage for the base. Parity p = tid>>6 is
// warp-uniform; each 64-lane group covers its parity's S2 pixels with
// NPX = S2/64 strided pixels/thread so weight float4s are loaded once
// (broadcast) per NPX pixels. Stage 4 is COUT=3-specialized.
// ---------------------------------------------------------------------------

// quadratic B-spline bases at v=0: {0, 1/8, 3/4, 1/8, 0}; relu(0)=0
#define F0A make_float4(0.0f, 0.125f, 0.75f, 0.125f)
#define F0B make_float2(0.0f, 0.0f)

__device__ __forceinline__ void spline_feats(float v, float4& fa, float2& fb) {
    const float H = 2.0f / 3.0f;
    float g[8];
#pragma unroll
    for (int i = 0; i < 8; i++) g[i] = (float)(i - 2) * H - 1.0f;
    float b0[7];
#pragma unroll
    for (int i = 0; i < 7; i++)
        b0[i] = (v >= g[i] && v < g[i + 1]) ? 1.0f : 0.0f;
    float b1[6];
#pragma unroll
    for (int i = 0; i < 6; i++)
        b1[i] = (v - g[i]) * (1.0f / (g[i + 1] - g[i])) * b0[i]
              + (g[i + 2] - v) * (1.0f / (g[i + 2] - g[i + 1])) * b0[i + 1];
    float b2[5];
#pragma unroll
    for (int i = 0; i < 5; i++)
        b2[i] = (v - g[i]) * (1.0f / (g[i + 2] - g[i])) * b1[i]
              + (g[i + 3] - v) * (1.0f / (g[i + 3] - g[i + 1])) * b1[i + 1];
    fa = make_float4(b2[0], b2[1], b2[2], b2[3]);
    fb = make_float2(b2[4], fmaxf(v, 0.0f));
}

template <int COUT>
__device__ __forceinline__ void fmaC(float s, float4 w, float4& a) {
    a.x = fmaf(s, w.x, a.x);
    a.y = fmaf(s, w.y, a.y);
    a.z = fmaf(s, w.z, a.z);
    if (COUT == 4) a.w = fmaf(s, w.w, a.w);
}

// ----------------------------- one conv stage ------------------------------
template <int HIN, int COUT, bool FINAL>
__device__ __forceinline__ void do_stage(
    const float* __restrict__ bw, const float* __restrict__ sw,
    float* act, float4* featA, float2* featB,
    float4* wsh4, float* gout)
{
    constexpr int S2   = HIN * HIN;
    constexpr int NSRC = 4 * S2;
    constexpr int HOUT = 2 * HIN;
    constexpr int HP   = HIN + 2;          // haloed width
    constexpr int S2P  = HP * HP;          // haloed slots per channel
    constexpr int NPX  = (S2 > 64) ? S2 / 64 : 1;
    constexpr int JSTR = (HIN >= 8) ? 64 / HIN : 1;  // row stride between j px
    const int tid = threadIdx.x;
    float* wsh = reinterpret_cast<float*>(wsh4);

    // --- build combined weights: W[p][pos][c][wf][co], wf: 0-4 spline, 5 relu
#pragma unroll
    for (int k = 0; k < 6; k++) {
        int e   = tid + k * 256;
        int co  = e & 3;
        int wf  = (e >> 2) % 6;
        int c   = (e / 24) & 3;
        int pos = (e / 96) & 3;
        int p   = e / 384;
        int py = p >> 1, px = p & 1;
        int ry = pos >> 1, rx = pos & 1;
        float s = 0.0f;
        if (co < COUT) {
            int ky0 = ry * (1 + py), nky = 1 + (ry ^ py);
            int kx0 = rx * (1 + px), nkx = 1 + (rx ^ px);
            for (int a = 0; a < nky; a++)
                for (int bb = 0; bb < nkx; bb++) {
                    int j = c * 9 + (ky0 + a) * 3 + (kx0 + bb);
                    s += (wf == 5) ? bw[co * 36 + j]
                                   : sw[(co * 36 + j) * 5 + wf];
                }
        }
        wsh[e] = s;
    }

    // --- border ring: spline(0) features (zero-padding contribution)
    {
        constexpr int NB = 2 * HP + 2 * HIN;   // ring cells per channel
        for (int e = tid; e < 4 * NB; e += 256) {
            int c = e / NB, r = e % NB;
            int y, x;
            if (r < 2 * HP) { y = (r < HP) ? 0 : HP - 1; x = (r < HP) ? r : r - HP; }
            else { int r2 = r - 2 * HP;
                   y = 1 + ((r2 < HIN) ? r2 : r2 - HIN);
                   x = (r2 < HIN) ? 0 : HP - 1; }
            int slot = c * S2P + y * HP + x;
            featA[slot] = F0A;
            featB[slot] = F0B;
        }
    }

    // --- featurize interior source values (reads act)
#pragma unroll
    for (int k = 0; k < (NSRC + 255) / 256; k++) {
        int lv = tid + k * 256;
        if (NSRC >= 256 || lv < NSRC) {
            int c = lv / S2, rem = lv % S2;
            int y = rem / HIN, x = rem % HIN;
            float4 fa; float2 fb;
            spline_feats(act[lv], fa, fb);
            int slot = c * S2P + (y + 1) * HP + (x + 1);
            featA[slot] = fa;
            featB[slot] = fb;
        }
    }
    __syncthreads();

    // --- phase C: pure LDS+FFMA, all offsets compile-time from one base
    const int p  = tid >> 6;       // warp-uniform parity
    const int l  = tid & 63;
    const int py = p >> 1, px = p & 1;

    if (S2 >= 64 || l < S2) {
        const int Yb = l / HIN;
        const int X  = l % HIN;
        // padded coords: sy = Yb + j*JSTR - 1 + py + ry -> row = sy+1
        const int base = (Yb + py) * HP + X + px;

        float4 acc[NPX];
#pragma unroll
        for (int j = 0; j < NPX; j++) acc[j] = make_float4(0.f, 0.f, 0.f, 0.f);

#pragma unroll
        for (int pos = 0; pos < 4; pos++) {
            const int ry = pos >> 1, rx = pos & 1;
            const float4* wp = wsh4 + (p * 4 + pos) * 24;
#pragma unroll
            for (int c = 0; c < 4; c++) {
                const int off = base + c * S2P + ry * HP + rx;
                float4 fa[NPX];
                float2 fb[NPX];
#pragma unroll
                for (int j = 0; j < NPX; j++) {
                    fa[j] = featA[off + j * JSTR * HP];
                    fb[j] = featB[off + j * JSTR * HP];
                }
                const float4* w = wp + c * 6;
#pragma unroll
                for (int f = 0; f < 6; f++) {
                    float4 wv = w[f];
#pragma unroll
                    for (int j = 0; j < NPX; j++) {
                        float s = (f == 0) ? fa[j].x : (f == 1) ? fa[j].y
                                : (f == 2) ? fa[j].z : (f == 3) ? fa[j].w
                                : (f == 4) ? fb[j].x : fb[j].y;
                        fmaC<COUT>(s, wv, acc[j]);
                    }
                }
            }
        }

        // --- write outputs
#pragma unroll
        for (int j = 0; j < NPX; j++) {
            int Y = Yb + j * JSTR;
            int y = 2 * Y + py, x = 2 * X + px;
            if (FINAL) {
                gout[0 * HOUT * HOUT + y * HOUT + x] = tanhf(acc[j].x);
                gout[1 * HOUT * HOUT + y * HOUT + x] = tanhf(acc[j].y);
                gout[2 * HOUT * HOUT + y * HOUT + x] = tanhf(acc[j].z);
            } else {
                act[0 * HOUT * HOUT + y * HOUT + x] = acc[j].x;
                act[1 * HOUT * HOUT + y * HOUT + x] = acc[j].y;
                act[2 * HOUT * HOUT + y * HOUT + x] = acc[j].z;
                act[3 * HOUT * HOUT + y * HOUT + x] = acc[j].w;
            }
        }
    }
    __syncthreads();   // act/wsh/feat stable before next stage
}

// ----------------------------- fused kernel --------------------------------
__global__ void __launch_bounds__(256, 4) fused_kan_kernel(
    const float* __restrict__ x,
    const float* __restrict__ lin_w,
    const float* __restrict__ lin_b,
    const float* __restrict__ bw1, const float* __restrict__ sw1,
    const float* __restrict__ bw2, const float* __restrict__ sw2,
    const float* __restrict__ bw3, const float* __restrict__ sw3,
    const float* __restrict__ bw4, const float* __restrict__ sw4,
    float* __restrict__ out)
{
    __shared__ float  act[1024];
    __shared__ float4 featA[4 * 18 * 18];   // haloed, stage-4 size (max)
    __shared__ float2 featB[4 * 18 * 18];
    __shared__ float4 wsh4[384];

    const int tid = threadIdx.x;
    const int b   = blockIdx.x;

    // linear + relu: 16 outputs, 4 threads each over 25-element chunks
    if (tid < 64) {
        int j = tid >> 2, qp = tid & 3;
        const float* xr = x + b * 100 + qp * 25;
        const float* wr = lin_w + j * 100 + qp * 25;
        float acc = 0.0f;
#pragma unroll
        for (int i = 0; i < 25; i++) acc = fmaf(xr[i], wr[i], acc);
        acc += __shfl_xor_sync(0xffffffffu, acc, 1);
        acc += __shfl_xor_sync(0xffffffffu, acc, 2);
        if (qp == 0) act[j] = fmaxf(acc + lin_b[j], 0.0f);
    }
    __syncthreads();

    do_stage<2, 4, false>(bw1, sw1, act, featA, featB, wsh4, nullptr);
    do_stage<4, 4, false>(bw2, sw2, act, featA, featB, wsh4, nullptr);
    do_stage<8, 4, false>(bw3, sw3, act, featA, featB, wsh4, nullptr);
    do_stage<16, 3, true>(bw4, sw4, act, featA, featB, wsh4,
                          out + (size_t)b * 3 * 32 * 32);
}

// ---------------------------------------------------------------------------
extern "C" void kernel_launch(void* const* d_in, const int* in_sizes, int n_in,
                              void* d_out, int out_size) {
    const float* x     = (const float*)d_in[0];
    const float* lin_w = (const float*)d_in[1];
    const float* lin_b = (const float*)d_in[2];
    const float* bw1   = (const float*)d_in[3];
    const float* sw1   = (const float*)d_in[4];
    const float* bw2   = (const float*)d_in[5];
    const float* sw2   = (const float*)d_in[6];
    const float* bw3   = (const float*)d_in[7];
    const float* sw3   = (const float*)d_in[8];
    const float* bw4   = (const float*)d_in[9];
    const float* sw4   = (const float*)d_in[10];

    fused_kan_kernel<<<512, 256>>>(x, lin_w, lin_b,
                                   bw1, sw1, bw2, sw2, bw3, sw3, bw4, sw4,
                                   (float*)d_out);
}